// round 1
// baseline (speedup 1.0000x reference)
#include <cuda_runtime.h>
#include <math.h>

// Problem constants
#define B_  2
#define S_  4096
#define D_  768
#define H_  12
#define DK_ 64
#define M_  (B_*S_)       // 8192

// ---------------- scratch (no allocation allowed) ----------------
__device__ float g_Q[B_*H_*S_*DK_];   // [B][H][S][Dk]
__device__ float g_K[B_*H_*S_*DK_];
__device__ float g_V[B_*H_*S_*DK_];
__device__ float g_ctx[(size_t)M_*D_]; // [B*S][D] (head-merged)

// ---------------- GEMM tiling ----------------
#define BM 64
#define BN 64
#define BK 32

// Fused QKV projection: y = x @ W^T + b, written head-split [B][H][S][Dk].
// grid: (D/BN=12=H, M/BM=128, 3), block (16,16)
__global__ __launch_bounds__(256) void qkv_kernel(
    const float* __restrict__ x,
    const float* __restrict__ Wq, const float* __restrict__ bq,
    const float* __restrict__ Wk, const float* __restrict__ bk,
    const float* __restrict__ Wv, const float* __restrict__ bv)
{
    const float* W; const float* bias; float* dst;
    int z = blockIdx.z;
    if (z == 0)      { W = Wq; bias = bq; dst = g_Q; }
    else if (z == 1) { W = Wk; bias = bk; dst = g_K; }
    else             { W = Wv; bias = bv; dst = g_V; }

    __shared__ float Xs[BK][BM+4];
    __shared__ float Ws[BK][BN+4];

    const int tx = threadIdx.x, ty = threadIdx.y;
    const int tid = ty*16 + tx;
    const int m0 = blockIdx.y * BM;
    const int n0 = blockIdx.x * BN;   // n0 = head*64 (BN == DK)

    float acc[4][4] = {};

    for (int k0 = 0; k0 < D_; k0 += BK) {
        #pragma unroll
        for (int c = 0; c < 2; c++) {               // X tile 64x32 (transposed store)
            int q   = tid + 256*c;                  // 0..511
            int row = q >> 3;
            int kc  = (q & 7) << 2;
            float4 v = *(const float4*)&x[(size_t)(m0+row)*D_ + k0 + kc];
            Xs[kc+0][row] = v.x; Xs[kc+1][row] = v.y;
            Xs[kc+2][row] = v.z; Xs[kc+3][row] = v.w;
        }
        #pragma unroll
        for (int c = 0; c < 2; c++) {               // W tile 64x32 (transposed store)
            int q   = tid + 256*c;
            int row = q >> 3;
            int kc  = (q & 7) << 2;
            float4 v = *(const float4*)&W[(size_t)(n0+row)*D_ + k0 + kc];
            Ws[kc+0][row] = v.x; Ws[kc+1][row] = v.y;
            Ws[kc+2][row] = v.z; Ws[kc+3][row] = v.w;
        }
        __syncthreads();
        #pragma unroll
        for (int kk = 0; kk < BK; kk++) {
            float4 a = *(const float4*)&Xs[kk][ty*4];
            float4 b = *(const float4*)&Ws[kk][tx*4];
            float av[4] = {a.x,a.y,a.z,a.w};
            float bv4[4] = {b.x,b.y,b.z,b.w};
            #pragma unroll
            for (int i = 0; i < 4; i++)
                #pragma unroll
                for (int j = 0; j < 4; j++)
                    acc[i][j] += av[i]*bv4[j];
        }
        __syncthreads();
    }

    const int h = blockIdx.x;
    #pragma unroll
    for (int i = 0; i < 4; i++) {
        int m  = m0 + ty*4 + i;
        int bb = m >> 12;          // /4096
        int ss = m & (S_-1);
        float4 o;
        o.x = acc[i][0] + bias[n0 + tx*4 + 0];
        o.y = acc[i][1] + bias[n0 + tx*4 + 1];
        o.z = acc[i][2] + bias[n0 + tx*4 + 2];
        o.w = acc[i][3] + bias[n0 + tx*4 + 3];
        *(float4*)&dst[(((size_t)bb*H_ + h)*S_ + ss)*DK_ + tx*4] = o;
    }
}

// Output projection: out = g_ctx @ Wo^T + bo (plain [B*S][D] layout)
// grid: (12, 128), block (16,16)
__global__ __launch_bounds__(256) void proj_kernel(
    const float* __restrict__ W, const float* __restrict__ bias,
    float* __restrict__ out)
{
    __shared__ float Xs[BK][BM+4];
    __shared__ float Ws[BK][BN+4];

    const int tx = threadIdx.x, ty = threadIdx.y;
    const int tid = ty*16 + tx;
    const int m0 = blockIdx.y * BM;
    const int n0 = blockIdx.x * BN;

    float acc[4][4] = {};

    for (int k0 = 0; k0 < D_; k0 += BK) {
        #pragma unroll
        for (int c = 0; c < 2; c++) {
            int q   = tid + 256*c;
            int row = q >> 3;
            int kc  = (q & 7) << 2;
            float4 v = *(const float4*)&g_ctx[(size_t)(m0+row)*D_ + k0 + kc];
            Xs[kc+0][row] = v.x; Xs[kc+1][row] = v.y;
            Xs[kc+2][row] = v.z; Xs[kc+3][row] = v.w;
        }
        #pragma unroll
        for (int c = 0; c < 2; c++) {
            int q   = tid + 256*c;
            int row = q >> 3;
            int kc  = (q & 7) << 2;
            float4 v = *(const float4*)&W[(size_t)(n0+row)*D_ + k0 + kc];
            Ws[kc+0][row] = v.x; Ws[kc+1][row] = v.y;
            Ws[kc+2][row] = v.z; Ws[kc+3][row] = v.w;
        }
        __syncthreads();
        #pragma unroll
        for (int kk = 0; kk < BK; kk++) {
            float4 a = *(const float4*)&Xs[kk][ty*4];
            float4 b = *(const float4*)&Ws[kk][tx*4];
            float av[4] = {a.x,a.y,a.z,a.w};
            float bv4[4] = {b.x,b.y,b.z,b.w};
            #pragma unroll
            for (int i = 0; i < 4; i++)
                #pragma unroll
                for (int j = 0; j < 4; j++)
                    acc[i][j] += av[i]*bv4[j];
        }
        __syncthreads();
    }

    #pragma unroll
    for (int i = 0; i < 4; i++) {
        int m = m0 + ty*4 + i;
        float4 o;
        o.x = acc[i][0] + bias[n0 + tx*4 + 0];
        o.y = acc[i][1] + bias[n0 + tx*4 + 1];
        o.z = acc[i][2] + bias[n0 + tx*4 + 2];
        o.w = acc[i][3] + bias[n0 + tx*4 + 3];
        *(float4*)&out[(size_t)m*D_ + n0 + tx*4] = o;
    }
}

// ---------------- Flash attention (fp32, online softmax) ----------------
// Per block: 64 query rows of one (b,h); stream keys in tiles of 32.
// grid: (S/64 = 64, B*H = 24), block (16,16)
#define AM 64
#define AN 32

__global__ __launch_bounds__(256) void attn_kernel()
{
    __shared__ float Qs[DK_][AM];      // Q^T  [d][row]
    __shared__ float Ks[DK_][AN];      // K^T  [d][key]
    __shared__ float Vs[AN][DK_];      // V    [key][d]
    __shared__ float Ps[AN][AM+4];     // P^T  [key][row]

    const int tx = threadIdx.x, ty = threadIdx.y;
    const int tid = ty*16 + tx;
    const int bh  = blockIdx.y;            // b*H + h
    const int m0  = blockIdx.x * AM;

    const float* Qg = g_Q + (size_t)bh*S_*DK_;
    const float* Kg = g_K + (size_t)bh*S_*DK_;
    const float* Vg = g_V + (size_t)bh*S_*DK_;

    // Load Q tile (transposed): 64x64
    #pragma unroll
    for (int c = 0; c < 4; c++) {
        int q   = tid + 256*c;             // 0..1023
        int row = q >> 4;
        int dc  = (q & 15) << 2;
        float4 v = *(const float4*)&Qg[(size_t)(m0+row)*DK_ + dc];
        Qs[dc+0][row] = v.x; Qs[dc+1][row] = v.y;
        Qs[dc+2][row] = v.z; Qs[dc+3][row] = v.w;
    }

    float o[4][4] = {};
    float mi[4], li[4];
    #pragma unroll
    for (int i = 0; i < 4; i++) { mi[i] = -1e30f; li[i] = 0.0f; }

    const float scale = 0.125f;  // 1/sqrt(64)

    for (int t = 0; t < S_/AN; t++) {
        __syncthreads();                   // prev PV done with Vs/Ps
        const int n0 = t * AN;
        #pragma unroll
        for (int c = 0; c < 2; c++) {      // K tile 32x64 (transposed store)
            int q   = tid + 256*c;         // 0..511
            int key = q >> 4;
            int dc  = (q & 15) << 2;
            float4 v = *(const float4*)&Kg[(size_t)(n0+key)*DK_ + dc];
            Ks[dc+0][key] = v.x; Ks[dc+1][key] = v.y;
            Ks[dc+2][key] = v.z; Ks[dc+3][key] = v.w;
        }
        #pragma unroll
        for (int c = 0; c < 2; c++) {      // V tile 32x64 (direct)
            int q   = tid + 256*c;
            int key = q >> 4;
            int dc  = (q & 15) << 2;
            *(float4*)&Vs[key][dc] = *(const float4*)&Vg[(size_t)(n0+key)*DK_ + dc];
        }
        __syncthreads();

        // S = Q K^T : thread tile 4 rows x 2 keys
        float s[4][2] = {};
        #pragma unroll
        for (int kk = 0; kk < DK_; kk++) {
            float4 a  = *(const float4*)&Qs[kk][ty*4];
            float2 b2 = *(const float2*)&Ks[kk][tx*2];
            s[0][0] += a.x*b2.x; s[0][1] += a.x*b2.y;
            s[1][0] += a.y*b2.x; s[1][1] += a.y*b2.y;
            s[2][0] += a.z*b2.x; s[2][1] += a.z*b2.y;
            s[3][0] += a.w*b2.x; s[3][1] += a.w*b2.y;
        }

        // Online softmax; row owned by the 16 tx lanes of a half-warp.
        #pragma unroll
        for (int i = 0; i < 4; i++) {
            s[i][0] *= scale; s[i][1] *= scale;
            float rm = fmaxf(s[i][0], s[i][1]);
            #pragma unroll
            for (int off = 8; off >= 1; off >>= 1)
                rm = fmaxf(rm, __shfl_xor_sync(0xffffffffu, rm, off));
            float mnew = fmaxf(mi[i], rm);
            float corr = __expf(mi[i] - mnew);
            float p0 = __expf(s[i][0] - mnew);
            float p1 = __expf(s[i][1] - mnew);
            float rs = p0 + p1;
            #pragma unroll
            for (int off = 8; off >= 1; off >>= 1)
                rs += __shfl_xor_sync(0xffffffffu, rs, off);
            li[i] = li[i]*corr + rs;
            mi[i] = mnew;
            #pragma unroll
            for (int j = 0; j < 4; j++) o[i][j] *= corr;
            s[i][0] = p0; s[i][1] = p1;
        }

        // P^T to smem
        #pragma unroll
        for (int j = 0; j < 2; j++)
            #pragma unroll
            for (int i = 0; i < 4; i++)
                Ps[tx*2+j][ty*4+i] = s[i][j];
        __syncthreads();

        // O += P V : thread tile 4 rows x 4 d
        #pragma unroll
        for (int n = 0; n < AN; n++) {
            float4 a  = *(const float4*)&Ps[n][ty*4];
            float4 b4 = *(const float4*)&Vs[n][tx*4];
            o[0][0]+=a.x*b4.x; o[0][1]+=a.x*b4.y; o[0][2]+=a.x*b4.z; o[0][3]+=a.x*b4.w;
            o[1][0]+=a.y*b4.x; o[1][1]+=a.y*b4.y; o[1][2]+=a.y*b4.z; o[1][3]+=a.y*b4.w;
            o[2][0]+=a.z*b4.x; o[2][1]+=a.z*b4.y; o[2][2]+=a.z*b4.z; o[2][3]+=a.z*b4.w;
            o[3][0]+=a.w*b4.x; o[3][1]+=a.w*b4.y; o[3][2]+=a.w*b4.z; o[3][3]+=a.w*b4.w;
        }
    }

    // Normalize and write context [B*S][D] with head-merged columns
    const int h  = bh % H_;
    const int bb = bh / H_;
    #pragma unroll
    for (int i = 0; i < 4; i++) {
        float inv = 1.0f / li[i];
        int srow = m0 + ty*4 + i;
        float4 ov;
        ov.x = o[i][0]*inv; ov.y = o[i][1]*inv;
        ov.z = o[i][2]*inv; ov.w = o[i][3]*inv;
        *(float4*)&g_ctx[((size_t)bb*S_ + srow)*D_ + h*DK_ + tx*4] = ov;
    }
}

// ---------------- launch ----------------
extern "C" void kernel_launch(void* const* d_in, const int* in_sizes, int n_in,
                              void* d_out, int out_size)
{
    const float* x  = (const float*)d_in[0];
    const float* Wq = (const float*)d_in[1];
    const float* bq = (const float*)d_in[2];
    const float* Wk = (const float*)d_in[3];
    const float* bk = (const float*)d_in[4];
    const float* Wv = (const float*)d_in[5];
    const float* bv = (const float*)d_in[6];
    const float* Wo = (const float*)d_in[7];
    const float* bo = (const float*)d_in[8];
    float* out = (float*)d_out;

    dim3 blk(16, 16);
    qkv_kernel<<<dim3(D_/BN, M_/BM, 3), blk>>>(x, Wq, bq, Wk, bk, Wv, bv);
    attn_kernel<<<dim3(S_/AM, B_*H_), blk>>>();
    proj_kernel<<<dim3(D_/BN, M_/BM), blk>>>(Wo, bo, out);
}